// round 1
// baseline (speedup 1.0000x reference)
#include <cuda_runtime.h>
#include <math.h>

#define LL 16
#define CC 32
#define HH 64
#define WW 64
#define WF 33
#define RR 16

// ---------------- scratch (device globals; no allocs allowed) ----------------
__device__ float d_f1[LL*CC*HH*WW];     // conv1 out (l,c,h,w)
__device__ float d_f2[LL*CC*HH*WW];     // conv2 out (l,c,h,w)
__device__ float d_glob[LL*CC];
__device__ float d_feat[LL*WF*CC];      // (l,f,c)
__device__ float d_Are[LL*CC*WF*RR];    // ((l*32+c)*33+f)*16+r
__device__ float d_Aim[LL*CC*WF*RR];
__device__ float d_S  [LL*CC*WF*RR];
__device__ float d_xfr[LL*CC*WF*HH];    // ((l*32+c)*33+f)*64+h
__device__ float d_xfi[LL*CC*WF*HH];
__device__ float d_yfr[LL*CC*WF*HH];
__device__ float d_yfi[LL*CC*WF*HH];
__device__ float d_ys [LL*CC*HH*WW];    // irfft out (l,c,h,w)
__device__ float d_y2 [LL*CC*HH*WW];    // pif out   (l,c,h,w)
__device__ float d_mu[LL*4];
__device__ float d_rstd[LL*4];
__device__ float d_gate[LL*CC*HH];      // (l,c,h)
__device__ float d_wr[CC];
__device__ float d_wi[CC];
__device__ float d_br;
__device__ float d_bi;

// ---------------- prep: collapse mix/rank_scale/proj into 64-weight dot ------
__global__ void k_prep(const float* __restrict__ mix_w, const float* __restrict__ mix_b,
                       const float* __restrict__ rs, const float* __restrict__ pw,
                       const float* __restrict__ pb)
{
    int j = threadIdx.x;  // 0..31
    float swr = 0.f, swi = 0.f;
    for (int r = 0; r < RR; r++) {
        float a = rs[r] * pw[r];
        swr += a * mix_w[r*32 + j];
        swi += a * mix_w[(16+r)*32 + j];
    }
    d_wr[j] = swr; d_wi[j] = swi;
    if (j == 0) {
        float br = pb[0], bi = 0.f;
        for (int r = 0; r < RR; r++) {
            float a = rs[r] * pw[r];
            br += a * mix_b[r];
            bi += a * mix_b[16+r];
        }
        d_br = br; d_bi = bi;
    }
}

// ---------------- conv 3x3 SAME + silu, 32->32 channels ----------------------
// grid (32 htiles, 16 l), block 64 threads; each thread computes 2 rows x 1 col,
// all 32 output channels accumulated in registers.
__device__ __forceinline__ void conv_body(const float* __restrict__ in, int in_base,
                                          int cstride,
                                          const float* __restrict__ wgt,
                                          const float* __restrict__ bias,
                                          float* __restrict__ out)
{
    __shared__ float wsm[32*32*9];   // [ci][co][9]
    __shared__ float tile[4*66];     // rows h0-1..h0+2, cols -1..64
    int l  = blockIdx.y;
    int h0 = blockIdx.x * 2;
    int tx = threadIdx.x;            // 0..63 (w)

    for (int i = tx; i < 32*32*9; i += 64) {
        int j = i % 9; int p = i / 9; int co = p & 31; int ci = p >> 5;
        wsm[(ci*32 + co)*9 + j] = wgt[co*288 + ci*9 + j];
    }

    float acc[2][32];
    #pragma unroll
    for (int a = 0; a < 2; a++)
        #pragma unroll
        for (int o = 0; o < 32; o++) acc[a][o] = 0.f;

    const float* inb = in + in_base;
    for (int ci = 0; ci < 32; ci++) {
        __syncthreads();
        for (int i = tx; i < 4*66; i += 64) {
            int r = i / 66, cc = i % 66;
            int gh = h0 - 1 + r, gw = cc - 1;
            float v = 0.f;
            if (gh >= 0 && gh < 64 && gw >= 0 && gw < 64)
                v = inb[ci*cstride + gh*64 + gw];
            tile[i] = v;
        }
        __syncthreads();
        float v[4][3];
        #pragma unroll
        for (int dy = 0; dy < 4; dy++)
            #pragma unroll
            for (int dx = 0; dx < 3; dx++)
                v[dy][dx] = tile[dy*66 + tx + dx];
        const float* wp = &wsm[ci*32*9];
        #pragma unroll
        for (int o = 0; o < 32; o++) {
            float w0 = wp[o*9+0], w1 = wp[o*9+1], w2 = wp[o*9+2];
            float w3 = wp[o*9+3], w4 = wp[o*9+4], w5 = wp[o*9+5];
            float w6 = wp[o*9+6], w7 = wp[o*9+7], w8 = wp[o*9+8];
            acc[0][o] += v[0][0]*w0 + v[0][1]*w1 + v[0][2]*w2
                       + v[1][0]*w3 + v[1][1]*w4 + v[1][2]*w5
                       + v[2][0]*w6 + v[2][1]*w7 + v[2][2]*w8;
            acc[1][o] += v[1][0]*w0 + v[1][1]*w1 + v[1][2]*w2
                       + v[2][0]*w3 + v[2][1]*w4 + v[2][2]*w5
                       + v[3][0]*w6 + v[3][1]*w7 + v[3][2]*w8;
        }
    }
    #pragma unroll
    for (int a = 0; a < 2; a++) {
        int h = h0 + a;
        #pragma unroll
        for (int o = 0; o < 32; o++) {
            float xv = acc[a][o] + bias[o];
            float s  = xv / (1.f + expf(-xv));   // silu
            out[((l*32 + o)*64 + h)*64 + tx] = s;
        }
    }
}

__global__ void k_conv1(const float* __restrict__ x, const float* __restrict__ w,
                        const float* __restrict__ b)
{
    // x layout (c,l,h,w): base = l*4096, channel stride = 16*4096
    conv_body(x, blockIdx.y * 4096, 16*4096, w, b, d_f1);
}
__global__ void k_conv2(const float* __restrict__ w, const float* __restrict__ b)
{
    // f1 layout (l,c,h,w): base = l*32*4096, channel stride = 4096
    conv_body(d_f1, blockIdx.y * 32 * 4096, 4096, w, b, d_f2);
}

// ---------------- global-pool gate: glob = sigmoid(mean_hw(f2) @ gfc_w.T + b) -
__global__ void k_glob(const float* __restrict__ gfc_w, const float* __restrict__ gfc_b)
{
    __shared__ float part[256];
    __shared__ float mean[32];
    int l = blockIdx.x, tid = threadIdx.x;
    int c = tid >> 3, s = tid & 7;
    const float* p = d_f2 + (l*32 + c)*4096 + s*512;
    float sum = 0.f;
    for (int i = 0; i < 512; i++) sum += p[i];
    part[tid] = sum;
    __syncthreads();
    if (tid < 32) {
        float m = 0.f;
        for (int k = 0; k < 8; k++) m += part[tid*8 + k];
        mean[tid] = m / 4096.f;
    }
    __syncthreads();
    if (tid < 32) {
        float a = gfc_b[tid];
        for (int ci = 0; ci < 32; ci++) a += mean[ci] * gfc_w[tid*32 + ci];
        d_glob[l*32 + tid] = 1.f / (1.f + expf(-a));
    }
}

// ---------------- mean over H + adaptive avg pool W->33, times glob ----------
// grid (32 c, 16 l), block 64
__global__ void k_feat()
{
    __shared__ float cs[64];
    int c = blockIdx.x, l = blockIdx.y, w = threadIdx.x;
    const float* p = d_f2 + (l*32 + c)*4096;
    float s = 0.f;
    for (int h = 0; h < 64; h++) s += p[h*64 + w];
    cs[w] = s;
    __syncthreads();
    if (w < WF) {
        int st = (w*64) / 33;
        int en = ((w+1)*64 + 32) / 33;   // ceil
        float sum = 0.f;
        for (int k = st; k < en; k++) sum += cs[k];
        d_feat[(l*33 + w)*32 + c] = d_glob[l*32 + c] * sum / (64.f * (float)(en - st));
    }
}

// ---------------- head matmul + nonlinearities -> A (complex), S -------------
// grid (33 f, 16 l), block 512 (thread = (c,r))
__global__ void k_head(const float* __restrict__ head_w, const float* __restrict__ head_b,
                       const float* __restrict__ dt)
{
    __shared__ float fl[32];
    int fi = blockIdx.x, l = blockIdx.y, tid = threadIdx.x;
    if (tid < 32) fl[tid] = d_feat[(l*33 + fi)*32 + tid];
    __syncthreads();
    int c = tid >> 4, r = tid & 15;
    int k0 = (c*16 + r)*3;
    float p[3];
    #pragma unroll
    for (int t = 0; t < 3; t++) {
        const float* wrow = head_w + (k0 + t)*32;
        float a = head_b[k0 + t];
        #pragma unroll
        for (int ci = 0; ci < 32; ci++) a += fl[ci] * wrow[ci];
        p[t] = a;
    }
    float dtl = dt[l];
    float nu = (p[0] > 20.f) ? p[0] : log1pf(expf(p[0]));
    float decay = expf(-nu * dtl);
    float ang = tanhf(p[1]) * 3.14159265358979323846f * dtl;
    float sa, ca;
    sincosf(ang, &sa, &ca);
    float sg = 1.f / (1.f + expf(-p[2]));
    float g  = 1.f - expf(-2.f * dtl);
    int idx = ((l*32 + c)*33 + fi)*16 + r;
    d_Are[idx] = decay * ca;
    d_Aim[idx] = decay * sa;
    d_S[idx]   = sg * g;
}

// ---------------- rfft over W (64 -> 33 bins), table-based DFT ---------------
// grid (32 c, 16 l), block 256
__global__ void k_rfft(const float* __restrict__ x)
{
    __shared__ float xs[4096];
    __shared__ float ct[64], st[64];
    int c = blockIdx.x, l = blockIdx.y, tid = threadIdx.x;
    if (tid < 64) { ct[tid] = cospif(tid / 32.f); st[tid] = sinpif(tid / 32.f); }
    const float* p = x + (size_t)(c*16 + l)*4096;
    for (int i = tid; i < 4096; i += 256) xs[i] = p[i];
    __syncthreads();
    for (int o = tid; o < WF*64; o += 256) {
        int f = o >> 6, h = o & 63;
        const float* row = xs + h*64;
        float re = 0.f, im = 0.f;
        int k = 0;
        for (int w = 0; w < 64; w++) {
            float v = row[w];
            re += v * ct[k];
            im -= v * st[k];
            k = (k + f) & 63;
        }
        int idx = ((l*32 + c)*33 + f)*64 + h;
        d_xfr[idx] = re; d_xfi[idx] = im;
    }
}

// ---------------- scan over L + collapsed mix/proj ---------------------------
// grid (33 f, 32 c), block 64 (thread = h); 16 complex rank-states in registers
__global__ void k_scan()
{
    __shared__ float sAr[256], sAi[256], sS[256];   // [l*16+r]
    __shared__ float swr[32], swi[32];
    int fi = blockIdx.x, c = blockIdx.y, h = threadIdx.x;
    for (int i = h; i < 256; i += 64) {
        int l = i >> 4, r = i & 15;
        int idx = ((l*32 + c)*33 + fi)*16 + r;
        sAr[i] = d_Are[idx]; sAi[i] = d_Aim[idx]; sS[i] = d_S[idx];
    }
    if (h < 32) { swr[h] = d_wr[h]; swi[h] = d_wi[h]; }
    __syncthreads();
    float br = d_br, bi = d_bi;
    float sr[16], si[16];
    #pragma unroll
    for (int r = 0; r < 16; r++) { sr[r] = 0.f; si[r] = 0.f; }
    for (int l = 0; l < 16; l++) {
        int xidx = ((l*32 + c)*33 + fi)*64 + h;
        float xr = d_xfr[xidx], xi = d_xfi[xidx];
        float yr = br, yi = bi;
        #pragma unroll
        for (int r = 0; r < 16; r++) {
            float ar = sAr[l*16 + r], ai = sAi[l*16 + r], s = sS[l*16 + r];
            float nr = ar*sr[r] - ai*si[r] + s*xr;
            float ni = ar*si[r] + ai*sr[r] + s*xi;
            sr[r] = nr; si[r] = ni;
            yr += swr[r]*nr + swr[16 + r]*ni;
            yi += swi[r]*nr + swi[16 + r]*ni;
        }
        d_yfr[xidx] = yr; d_yfi[xidx] = yi;
    }
}

// ---------------- irfft (33 -> 64), table-based ------------------------------
// grid (32 c, 16 l), block 256
__global__ void k_irfft()
{
    __shared__ float yr[WF*64], yi[WF*64];
    __shared__ float ct[64], st[64];
    int c = blockIdx.x, l = blockIdx.y, tid = threadIdx.x;
    if (tid < 64) { ct[tid] = cospif(tid / 32.f); st[tid] = sinpif(tid / 32.f); }
    int base = ((l*32 + c)*33)*64;
    for (int i = tid; i < WF*64; i += 256) { yr[i] = d_yfr[base + i]; yi[i] = d_yfi[base + i]; }
    __syncthreads();
    for (int o = tid; o < 4096; o += 256) {
        int h = o >> 6, w = o & 63;
        float sum = yr[h];                           // f=0 (real part only)
        sum += (w & 1) ? -yr[32*64 + h] : yr[32*64 + h];  // f=32, cos(pi*w)
        int k = w & 63;
        for (int f = 1; f < 32; f++) {
            sum += 2.f * (yr[f*64 + h] * ct[k] - yi[f*64 + h] * st[k]);
            k = (k + w) & 63;
        }
        d_ys[(l*32 + c)*4096 + o] = sum * (1.f / 64.f);
    }
}

// ---------------- pif 1x1 channel mix ----------------------------------------
// grid (16 htiles, 16 l), block 128; each thread 2 pixels, all 32 outputs
__global__ void k_pif(const float* __restrict__ pw, const float* __restrict__ pb)
{
    __shared__ float xin[32][256];
    __shared__ float wsm[32*32];
    __shared__ float bsm[32];
    int l = blockIdx.y, h0 = blockIdx.x*4;
    int tid = threadIdx.x;
    for (int i = tid; i < 1024; i += 128) wsm[i] = pw[i];
    if (tid < 32) bsm[tid] = pb[tid];
    int base = l*32*4096 + h0*64;
    for (int c = 0; c < 32; c++) {
        xin[c][tid]       = d_ys[base + c*4096 + tid];
        xin[c][tid + 128] = d_ys[base + c*4096 + tid + 128];
    }
    __syncthreads();
    float x0[32], x1[32];
    #pragma unroll
    for (int c2 = 0; c2 < 32; c2++) { x0[c2] = xin[c2][tid]; x1[c2] = xin[c2][tid + 128]; }
    #pragma unroll 4
    for (int o = 0; o < 32; o++) {
        float a0 = bsm[o], a1 = bsm[o];
        #pragma unroll
        for (int c2 = 0; c2 < 32; c2++) {
            float wv = wsm[o*32 + c2];
            a0 += wv * x0[c2];
            a1 += wv * x1[c2];
        }
        d_y2[base + o*4096 + tid]       = a0;
        d_y2[base + o*4096 + tid + 128] = a1;
    }
}

// ---------------- group-norm stats -------------------------------------------
// grid (4 g, 16 l), block 256
__global__ void k_gstats()
{
    __shared__ float ps[256], ps2[256];
    int g = blockIdx.x, l = blockIdx.y, tid = threadIdx.x;
    const float* p = d_y2 + (l*32 + g*8)*4096;
    float s = 0.f, s2 = 0.f;
    for (int i = tid; i < 8*4096; i += 256) { float v = p[i]; s += v; s2 += v*v; }
    ps[tid] = s; ps2[tid] = s2;
    __syncthreads();
    for (int off = 128; off > 0; off >>= 1) {
        if (tid < off) { ps[tid] += ps[tid + off]; ps2[tid] += ps2[tid + off]; }
        __syncthreads();
    }
    if (tid == 0) {
        float mu  = ps[0] / 32768.f;
        float var = ps2[0] / 32768.f - mu*mu;
        d_mu[l*4 + g]   = mu;
        d_rstd[l*4 + g] = rsqrtf(var + 1e-5f);
    }
}

// ---------------- gate MLP per (l,h) -----------------------------------------
// grid (64 h, 16 l), block 64
__global__ void k_gate(const float* __restrict__ gn_w, const float* __restrict__ gn_b,
                       const float* __restrict__ g1w, const float* __restrict__ g1b,
                       const float* __restrict__ g2w, const float* __restrict__ g2b)
{
    __shared__ float red[64];
    __shared__ float ym[32];
    __shared__ float hid[4];
    int hh = blockIdx.x, l = blockIdx.y, tid = threadIdx.x;
    for (int c = 0; c < 32; c++) {
        red[tid] = d_y2[(l*32 + c)*4096 + hh*64 + tid];
        __syncthreads();
        if (tid < 32) {
            float v = red[tid] + red[tid + 32];
            for (int off = 16; off > 0; off >>= 1)
                v += __shfl_down_sync(0xffffffffu, v, off);
            if (tid == 0) {
                int g = c >> 3;
                ym[c] = ((v / 64.f) - d_mu[l*4 + g]) * d_rstd[l*4 + g] * gn_w[c] + gn_b[c];
            }
        }
        __syncthreads();
    }
    if (tid < 4) {
        float a = g1b[tid];
        for (int c = 0; c < 32; c++) a += g1w[tid*32 + c] * ym[c];
        hid[tid] = a / (1.f + expf(-a));   // silu
    }
    __syncthreads();
    if (tid < 32) {
        float a = g2b[tid];
        for (int m = 0; m < 4; m++) a += g2w[tid*4 + m] * hid[m];
        d_gate[(l*32 + tid)*64 + hh] = 1.f / (1.f + expf(-a));
    }
}

// ---------------- final: normalize + gate + residual -------------------------
// grid 8192, block 256; index over (c,l,h,w)
__global__ void k_out(const float* __restrict__ x, const float* __restrict__ gn_w,
                      const float* __restrict__ gn_b, float* __restrict__ out)
{
    int i = blockIdx.x * 256 + threadIdx.x;
    int w = i & 63;
    int h = (i >> 6) & 63;
    int l = (i >> 12) & 15;
    int c = i >> 16;
    int yidx = (l*32 + c)*4096 + h*64 + w;
    int g = c >> 3;
    float z = (d_y2[yidx] - d_mu[l*4 + g]) * d_rstd[l*4 + g] * gn_w[c] + gn_b[c];
    out[i] = x[i] + z * d_gate[(l*32 + c)*64 + h];
}

// ---------------- launch -----------------------------------------------------
extern "C" void kernel_launch(void* const* d_in, const int* in_sizes, int n_in,
                              void* d_out, int out_size)
{
    const float* x       = (const float*)d_in[0];
    const float* dt      = (const float*)d_in[1];
    const float* conv1_w = (const float*)d_in[2];
    const float* conv1_b = (const float*)d_in[3];
    const float* conv2_w = (const float*)d_in[4];
    const float* conv2_b = (const float*)d_in[5];
    const float* gfc_w   = (const float*)d_in[6];
    const float* gfc_b   = (const float*)d_in[7];
    const float* head_w  = (const float*)d_in[8];
    const float* head_b  = (const float*)d_in[9];
    const float* mix_w   = (const float*)d_in[10];
    const float* mix_b   = (const float*)d_in[11];
    const float* rank_s  = (const float*)d_in[12];
    const float* proj_w  = (const float*)d_in[13];
    const float* proj_b  = (const float*)d_in[14];
    const float* pif_w   = (const float*)d_in[15];
    const float* pif_b   = (const float*)d_in[16];
    const float* gn_w    = (const float*)d_in[17];
    const float* gn_b    = (const float*)d_in[18];
    const float* g1_w    = (const float*)d_in[19];
    const float* g1_b    = (const float*)d_in[20];
    const float* g2_w    = (const float*)d_in[21];
    const float* g2_b    = (const float*)d_in[22];
    float* out = (float*)d_out;

    k_prep<<<1, 32>>>(mix_w, mix_b, rank_s, proj_w, proj_b);
    k_conv1<<<dim3(32, 16), 64>>>(x, conv1_w, conv1_b);
    k_conv2<<<dim3(32, 16), 64>>>(conv2_w, conv2_b);
    k_glob<<<16, 256>>>(gfc_w, gfc_b);
    k_feat<<<dim3(32, 16), 64>>>();
    k_head<<<dim3(33, 16), 512>>>(head_w, head_b, dt);
    k_rfft<<<dim3(32, 16), 256>>>(x);
    k_scan<<<dim3(33, 32), 64>>>();
    k_irfft<<<dim3(32, 16), 256>>>();
    k_pif<<<dim3(16, 16), 128>>>(pif_w, pif_b);
    k_gstats<<<dim3(4, 16), 256>>>();
    k_gate<<<dim3(64, 16), 64>>>(gn_w, gn_b, g1_w, g1_b, g2_w, g2_b);
    k_out<<<8192, 256>>>(x, gn_w, gn_b, out);
}

// round 2
// speedup vs baseline: 1.1799x; 1.1799x over previous
#include <cuda_runtime.h>
#include <math.h>

#define LL 16
#define CC 32
#define HH 64
#define WW 64
#define WF 33
#define RR 16

// ---------------- scratch (device globals; no allocs allowed) ----------------
__device__ float d_f1[LL*CC*HH*WW];     // conv1 out (l,c,h,w)
__device__ float d_f2[LL*CC*HH*WW];     // conv2 out (l,c,h,w)
__device__ float d_cmean[LL*CC];        // per (l,c) spatial mean of f2
__device__ float d_cs[LL*CC*WW];        // per (l,c) column sums over h
__device__ float d_feat[LL*WF*CC];      // (l,f,c)
__device__ float d_Are[LL*CC*WF*RR];
__device__ float d_Aim[LL*CC*WF*RR];
__device__ float d_S  [LL*CC*WF*RR];
__device__ float d_xfr[LL*CC*WF*HH];
__device__ float d_xfi[LL*CC*WF*HH];
__device__ float d_yfr[LL*CC*WF*HH];
__device__ float d_yfi[LL*CC*WF*HH];
__device__ float d_ys [LL*CC*HH*WW];    // irfft out (l,c,h,w)
__device__ float d_y2 [LL*CC*HH*WW];    // pif out   (l,c,h,w)
__device__ float d_mu[LL*4];
__device__ float d_rstd[LL*4];
__device__ float d_ymean[LL*CC*HH];     // raw mean over w of y2
__device__ float d_gate[LL*CC*HH];      // (l,c,h)
__device__ float d_wr[CC];
__device__ float d_wi[CC];
__device__ float d_br;
__device__ float d_bi;

// ---------------- prep: collapse mix/rank_scale/proj into 64-weight dot ------
__global__ void k_prep(const float* __restrict__ mix_w, const float* __restrict__ mix_b,
                       const float* __restrict__ rs, const float* __restrict__ pw,
                       const float* __restrict__ pb)
{
    int j = threadIdx.x;  // 0..31
    float swr = 0.f, swi = 0.f;
    for (int r = 0; r < RR; r++) {
        float a = rs[r] * pw[r];
        swr += a * mix_w[r*32 + j];
        swi += a * mix_w[(16+r)*32 + j];
    }
    d_wr[j] = swr; d_wi[j] = swi;
    if (j == 0) {
        float br = pb[0], bi = 0.f;
        for (int r = 0; r < RR; r++) {
            float a = rs[r] * pw[r];
            br += a * mix_b[r];
            bi += a * mix_b[16+r];
        }
        d_br = br; d_bi = bi;
    }
}

// ---------------- conv 3x3 SAME + silu, 32->32 ch, double-buffered tiles -----
// grid (16 htiles, 16 l), block 128 (64 w x 2 hgroups), thread computes 2 rows.
__device__ __forceinline__ void conv_body(const float* __restrict__ in, int in_base,
                                          int cstride,
                                          const float* __restrict__ wgt,
                                          const float* __restrict__ bias,
                                          float* __restrict__ out)
{
    __shared__ float wsm[32*32*9];     // [ci][co][9]
    __shared__ float tile[2][6*66];    // rows h0-1..h0+4, cols -1..64
    int l  = blockIdx.y;
    int h0 = blockIdx.x * 4;
    int tid = threadIdx.x;
    int tx = tid & 63;                 // w
    int ty = tid >> 6;                 // 0..1

    for (int i = tid; i < 32*32*9; i += 128) {
        int j = i % 9; int p = i / 9; int co = p & 31; int ci = p >> 5;
        wsm[(ci*32 + co)*9 + j] = wgt[co*288 + ci*9 + j];
    }

    const float* inb = in + in_base;
    for (int i = tid; i < 6*66; i += 128) {
        int r = i / 66, cc = i % 66;
        int gh = h0 - 1 + r, gw = cc - 1;
        float v = 0.f;
        if (gh >= 0 && gh < 64 && gw >= 0 && gw < 64)
            v = inb[gh*64 + gw];
        tile[0][i] = v;
    }
    __syncthreads();

    float acc[2][32];
    #pragma unroll
    for (int a = 0; a < 2; a++)
        #pragma unroll
        for (int o = 0; o < 32; o++) acc[a][o] = 0.f;

    for (int ci = 0; ci < 32; ci++) {
        int cur = ci & 1;
        if (ci + 1 < 32) {                           // prefetch next channel tile
            const float* src = inb + (ci + 1) * cstride;
            for (int i = tid; i < 6*66; i += 128) {
                int r = i / 66, cc = i % 66;
                int gh = h0 - 1 + r, gw = cc - 1;
                float v = 0.f;
                if (gh >= 0 && gh < 64 && gw >= 0 && gw < 64)
                    v = src[gh*64 + gw];
                tile[cur ^ 1][i] = v;
            }
        }
        float v[4][3];
        #pragma unroll
        for (int dy = 0; dy < 4; dy++)
            #pragma unroll
            for (int dx = 0; dx < 3; dx++)
                v[dy][dx] = tile[cur][(ty*2 + dy)*66 + tx + dx];
        const float* wp = &wsm[ci*32*9];
        #pragma unroll
        for (int o = 0; o < 32; o++) {
            float w0 = wp[o*9+0], w1 = wp[o*9+1], w2 = wp[o*9+2];
            float w3 = wp[o*9+3], w4 = wp[o*9+4], w5 = wp[o*9+5];
            float w6 = wp[o*9+6], w7 = wp[o*9+7], w8 = wp[o*9+8];
            acc[0][o] += v[0][0]*w0 + v[0][1]*w1 + v[0][2]*w2
                       + v[1][0]*w3 + v[1][1]*w4 + v[1][2]*w5
                       + v[2][0]*w6 + v[2][1]*w7 + v[2][2]*w8;
            acc[1][o] += v[1][0]*w0 + v[1][1]*w1 + v[1][2]*w2
                       + v[2][0]*w3 + v[2][1]*w4 + v[2][2]*w5
                       + v[3][0]*w6 + v[3][1]*w7 + v[3][2]*w8;
        }
        __syncthreads();
    }
    #pragma unroll
    for (int a = 0; a < 2; a++) {
        int h = h0 + ty*2 + a;
        #pragma unroll
        for (int o = 0; o < 32; o++) {
            float xv = acc[a][o] + bias[o];
            float s  = xv / (1.f + expf(-xv));   // silu
            out[((l*32 + o)*64 + h)*64 + tx] = s;
        }
    }
}

__global__ void k_conv1(const float* __restrict__ x, const float* __restrict__ w,
                        const float* __restrict__ b)
{
    // x layout (c,l,h,w): base = l*4096, channel stride = 16*4096
    conv_body(x, blockIdx.y * 4096, 16*4096, w, b, d_f1);
}
__global__ void k_conv2(const float* __restrict__ w, const float* __restrict__ b)
{
    // f1 layout (l,c,h,w): base = l*32*4096, channel stride = 4096
    conv_body(d_f1, blockIdx.y * 32 * 4096, 4096, w, b, d_f2);
}

// ---------------- fused reductions over f2: channel mean + column sums -------
// grid 512 ((l,c)), block 256; coalesced load into padded smem
__global__ void k_sum()
{
    __shared__ float xs[64*65];
    __shared__ float red[8];
    int lc = blockIdx.x, tid = threadIdx.x;
    const float* p = d_f2 + lc*4096;
    float s = 0.f;
    for (int i = tid; i < 4096; i += 256) {
        float v = p[i];
        xs[(i >> 6)*65 + (i & 63)] = v;
        s += v;
    }
    #pragma unroll
    for (int off = 16; off > 0; off >>= 1) s += __shfl_down_sync(0xffffffffu, s, off);
    if ((tid & 31) == 0) red[tid >> 5] = s;
    __syncthreads();
    if (tid == 0) {
        float t = 0.f;
        #pragma unroll
        for (int k = 0; k < 8; k++) t += red[k];
        d_cmean[lc] = t / 4096.f;
    }
    if (tid < 64) {
        float cs = 0.f;
        #pragma unroll 8
        for (int h = 0; h < 64; h++) cs += xs[h*65 + tid];
        d_cs[lc*64 + tid] = cs;
    }
}

// ---------------- glob matvec + adaptive pool W->33 --------------------------
// grid 16 (l), block 256
__global__ void k_featglob(const float* __restrict__ gfc_w, const float* __restrict__ gfc_b)
{
    __shared__ float cm[32];
    __shared__ float gl[32];
    int l = blockIdx.x, tid = threadIdx.x;
    if (tid < 32) cm[tid] = d_cmean[l*32 + tid];
    __syncthreads();
    if (tid < 32) {
        float a = gfc_b[tid];
        #pragma unroll
        for (int ci = 0; ci < 32; ci++) a += cm[ci] * gfc_w[tid*32 + ci];
        gl[tid] = 1.f / (1.f + expf(-a));
    }
    __syncthreads();
    for (int o = tid; o < WF*32; o += 256) {
        int c = o & 31, f = o >> 5;
        int st = (f*64) / 33;
        int en = ((f+1)*64 + 32) / 33;   // ceil
        float sum = 0.f;
        for (int k = st; k < en; k++) sum += d_cs[(l*32 + c)*64 + k];
        d_feat[(l*33 + f)*32 + c] = gl[c] * sum / (64.f * (float)(en - st));
    }
}

// ---------------- head matmul + nonlinearities -> A (complex), S -------------
__global__ void k_head(const float* __restrict__ head_w, const float* __restrict__ head_b,
                       const float* __restrict__ dt)
{
    __shared__ float fl[32];
    int fi = blockIdx.x, l = blockIdx.y, tid = threadIdx.x;
    if (tid < 32) fl[tid] = d_feat[(l*33 + fi)*32 + tid];
    __syncthreads();
    int c = tid >> 4, r = tid & 15;
    int k0 = (c*16 + r)*3;
    float p[3];
    #pragma unroll
    for (int t = 0; t < 3; t++) {
        const float* wrow = head_w + (k0 + t)*32;
        float a = head_b[k0 + t];
        #pragma unroll
        for (int ci = 0; ci < 32; ci++) a += fl[ci] * wrow[ci];
        p[t] = a;
    }
    float dtl = dt[l];
    float nu = (p[0] > 20.f) ? p[0] : log1pf(expf(p[0]));
    float decay = expf(-nu * dtl);
    float ang = tanhf(p[1]) * 3.14159265358979323846f * dtl;
    float sa, ca;
    sincosf(ang, &sa, &ca);
    float sg = 1.f / (1.f + expf(-p[2]));
    float g  = 1.f - expf(-2.f * dtl);
    int idx = ((l*32 + c)*33 + fi)*16 + r;
    d_Are[idx] = decay * ca;
    d_Aim[idx] = decay * sa;
    d_S[idx]   = sg * g;
}

// ---------------- rfft over W (64 -> 33 bins), table-based DFT ---------------
__global__ void k_rfft(const float* __restrict__ x)
{
    __shared__ float xs[4096];
    __shared__ float ct[64], st[64];
    int c = blockIdx.x, l = blockIdx.y, tid = threadIdx.x;
    if (tid < 64) { ct[tid] = cospif(tid / 32.f); st[tid] = sinpif(tid / 32.f); }
    const float* p = x + (size_t)(c*16 + l)*4096;
    for (int i = tid; i < 4096; i += 256) xs[i] = p[i];
    __syncthreads();
    for (int o = tid; o < WF*64; o += 256) {
        int f = o >> 6, h = o & 63;
        const float* row = xs + h*64;
        float re = 0.f, im = 0.f;
        int k = 0;
        for (int w = 0; w < 64; w++) {
            float v = row[w];
            re += v * ct[k];
            im -= v * st[k];
            k = (k + f) & 63;
        }
        int idx = ((l*32 + c)*33 + f)*64 + h;
        d_xfr[idx] = re; d_xfi[idx] = im;
    }
}

// ---------------- scan over L + collapsed mix/proj ---------------------------
__global__ void k_scan()
{
    __shared__ float sAr[256], sAi[256], sS[256];
    __shared__ float swr[32], swi[32];
    int fi = blockIdx.x, c = blockIdx.y, h = threadIdx.x;
    for (int i = h; i < 256; i += 64) {
        int l = i >> 4, r = i & 15;
        int idx = ((l*32 + c)*33 + fi)*16 + r;
        sAr[i] = d_Are[idx]; sAi[i] = d_Aim[idx]; sS[i] = d_S[idx];
    }
    if (h < 32) { swr[h] = d_wr[h]; swi[h] = d_wi[h]; }
    __syncthreads();
    float br = d_br, bi = d_bi;
    float sr[16], si[16];
    #pragma unroll
    for (int r = 0; r < 16; r++) { sr[r] = 0.f; si[r] = 0.f; }
    for (int l = 0; l < 16; l++) {
        int xidx = ((l*32 + c)*33 + fi)*64 + h;
        float xr = d_xfr[xidx], xi = d_xfi[xidx];
        float yr = br, yi = bi;
        #pragma unroll
        for (int r = 0; r < 16; r++) {
            float ar = sAr[l*16 + r], ai = sAi[l*16 + r], s = sS[l*16 + r];
            float nr = ar*sr[r] - ai*si[r] + s*xr;
            float ni = ar*si[r] + ai*sr[r] + s*xi;
            sr[r] = nr; si[r] = ni;
            yr += swr[r]*nr + swr[16 + r]*ni;
            yi += swi[r]*nr + swi[16 + r]*ni;
        }
        d_yfr[xidx] = yr; d_yfi[xidx] = yi;
    }
}

// ---------------- irfft (33 -> 64), table-based ------------------------------
__global__ void k_irfft()
{
    __shared__ float yr[WF*64], yi[WF*64];
    __shared__ float ct[64], st[64];
    int c = blockIdx.x, l = blockIdx.y, tid = threadIdx.x;
    if (tid < 64) { ct[tid] = cospif(tid / 32.f); st[tid] = sinpif(tid / 32.f); }
    int base = ((l*32 + c)*33)*64;
    for (int i = tid; i < WF*64; i += 256) { yr[i] = d_yfr[base + i]; yi[i] = d_yfi[base + i]; }
    __syncthreads();
    for (int o = tid; o < 4096; o += 256) {
        int h = o >> 6, w = o & 63;
        float sum = yr[h];
        sum += (w & 1) ? -yr[32*64 + h] : yr[32*64 + h];
        int k = w & 63;
        for (int f = 1; f < 32; f++) {
            sum += 2.f * (yr[f*64 + h] * ct[k] - yi[f*64 + h] * st[k]);
            k = (k + w) & 63;
        }
        d_ys[(l*32 + c)*4096 + o] = sum * (1.f / 64.f);
    }
}

// ---------------- pif 1x1 channel mix ----------------------------------------
__global__ void k_pif(const float* __restrict__ pw, const float* __restrict__ pb)
{
    __shared__ float xin[32][256];
    __shared__ float wsm[32*32];
    __shared__ float bsm[32];
    int l = blockIdx.y, h0 = blockIdx.x*4;
    int tid = threadIdx.x;
    for (int i = tid; i < 1024; i += 128) wsm[i] = pw[i];
    if (tid < 32) bsm[tid] = pb[tid];
    int base = l*32*4096 + h0*64;
    for (int c = 0; c < 32; c++) {
        xin[c][tid]       = d_ys[base + c*4096 + tid];
        xin[c][tid + 128] = d_ys[base + c*4096 + tid + 128];
    }
    __syncthreads();
    float x0[32], x1[32];
    #pragma unroll
    for (int c2 = 0; c2 < 32; c2++) { x0[c2] = xin[c2][tid]; x1[c2] = xin[c2][tid + 128]; }
    #pragma unroll 4
    for (int o = 0; o < 32; o++) {
        float a0 = bsm[o], a1 = bsm[o];
        #pragma unroll
        for (int c2 = 0; c2 < 32; c2++) {
            float wv = wsm[o*32 + c2];
            a0 += wv * x0[c2];
            a1 += wv * x1[c2];
        }
        d_y2[base + o*4096 + tid]       = a0;
        d_y2[base + o*4096 + tid + 128] = a1;
    }
}

// ---------------- group-norm stats -------------------------------------------
__global__ void k_gstats()
{
    __shared__ float ps[256], ps2[256];
    int g = blockIdx.x, l = blockIdx.y, tid = threadIdx.x;
    const float* p = d_y2 + (l*32 + g*8)*4096;
    float s = 0.f, s2 = 0.f;
    for (int i = tid; i < 8*4096; i += 256) { float v = p[i]; s += v; s2 += v*v; }
    ps[tid] = s; ps2[tid] = s2;
    __syncthreads();
    for (int off = 128; off > 0; off >>= 1) {
        if (tid < off) { ps[tid] += ps[tid + off]; ps2[tid] += ps2[tid + off]; }
        __syncthreads();
    }
    if (tid == 0) {
        float mu  = ps[0] / 32768.f;
        float var = ps2[0] / 32768.f - mu*mu;
        d_mu[l*4 + g]   = mu;
        d_rstd[l*4 + g] = rsqrtf(var + 1e-5f);
    }
}

// ---------------- row means over w of y2 (for gate MLP) ----------------------
// grid 512 ((l,c)), block 256
__global__ void k_rowmean()
{
    __shared__ float xs[64*65];
    int lc = blockIdx.x, tid = threadIdx.x;
    const float* p = d_y2 + lc*4096;
    for (int i = tid; i < 4096; i += 256)
        xs[(i >> 6)*65 + (i & 63)] = p[i];
    __syncthreads();
    if (tid < 64) {
        float s = 0.f;
        #pragma unroll 8
        for (int w = 0; w < 64; w++) s += xs[tid*65 + w];
        d_ymean[lc*64 + tid] = s / 64.f;
    }
}

// ---------------- gate MLP per (l,h) -----------------------------------------
// grid 16 (l), block 64 (h)
__global__ void k_gatemlp(const float* __restrict__ gn_w, const float* __restrict__ gn_b,
                          const float* __restrict__ g1w, const float* __restrict__ g1b,
                          const float* __restrict__ g2w, const float* __restrict__ g2b)
{
    int l = blockIdx.x, h = threadIdx.x;
    float hid[4];
    #pragma unroll
    for (int m = 0; m < 4; m++) hid[m] = g1b[m];
    #pragma unroll
    for (int c = 0; c < 32; c++) {
        int g = c >> 3;
        float ym = (d_ymean[(l*32 + c)*64 + h] - d_mu[l*4 + g]) * d_rstd[l*4 + g]
                   * gn_w[c] + gn_b[c];
        #pragma unroll
        for (int m = 0; m < 4; m++) hid[m] += g1w[m*32 + c] * ym;
    }
    #pragma unroll
    for (int m = 0; m < 4; m++) hid[m] = hid[m] / (1.f + expf(-hid[m]));  // silu
    #pragma unroll
    for (int c = 0; c < 32; c++) {
        float a = g2b[c];
        #pragma unroll
        for (int m = 0; m < 4; m++) a += g2w[c*4 + m] * hid[m];
        d_gate[(l*32 + c)*64 + h] = 1.f / (1.f + expf(-a));
    }
}

// ---------------- final: normalize + gate + residual -------------------------
__global__ void k_out(const float* __restrict__ x, const float* __restrict__ gn_w,
                      const float* __restrict__ gn_b, float* __restrict__ out)
{
    int i = blockIdx.x * 256 + threadIdx.x;
    int w = i & 63;
    int h = (i >> 6) & 63;
    int l = (i >> 12) & 15;
    int c = i >> 16;
    int yidx = (l*32 + c)*4096 + h*64 + w;
    int g = c >> 3;
    float z = (d_y2[yidx] - d_mu[l*4 + g]) * d_rstd[l*4 + g] * gn_w[c] + gn_b[c];
    out[i] = x[i] + z * d_gate[(l*32 + c)*64 + h];
}

// ---------------- launch -----------------------------------------------------
extern "C" void kernel_launch(void* const* d_in, const int* in_sizes, int n_in,
                              void* d_out, int out_size)
{
    const float* x       = (const float*)d_in[0];
    const float* dt      = (const float*)d_in[1];
    const float* conv1_w = (const float*)d_in[2];
    const float* conv1_b = (const float*)d_in[3];
    const float* conv2_w = (const float*)d_in[4];
    const float* conv2_b = (const float*)d_in[5];
    const float* gfc_w   = (const float*)d_in[6];
    const float* gfc_b   = (const float*)d_in[7];
    const float* head_w  = (const float*)d_in[8];
    const float* head_b  = (const float*)d_in[9];
    const float* mix_w   = (const float*)d_in[10];
    const float* mix_b   = (const float*)d_in[11];
    const float* rank_s  = (const float*)d_in[12];
    const float* proj_w  = (const float*)d_in[13];
    const float* proj_b  = (const float*)d_in[14];
    const float* pif_w   = (const float*)d_in[15];
    const float* pif_b   = (const float*)d_in[16];
    const float* gn_w    = (const float*)d_in[17];
    const float* gn_b    = (const float*)d_in[18];
    const float* g1_w    = (const float*)d_in[19];
    const float* g1_b    = (const float*)d_in[20];
    const float* g2_w    = (const float*)d_in[21];
    const float* g2_b    = (const float*)d_in[22];
    float* out = (float*)d_out;

    k_prep<<<1, 32>>>(mix_w, mix_b, rank_s, proj_w, proj_b);
    k_conv1<<<dim3(16, 16), 128>>>(x, conv1_w, conv1_b);
    k_conv2<<<dim3(16, 16), 128>>>(conv2_w, conv2_b);
    k_sum<<<512, 256>>>();
    k_featglob<<<16, 256>>>(gfc_w, gfc_b);
    k_head<<<dim3(33, 16), 512>>>(head_w, head_b, dt);
    k_rfft<<<dim3(32, 16), 256>>>(x);
    k_scan<<<dim3(33, 32), 64>>>();
    k_irfft<<<dim3(32, 16), 256>>>();
    k_pif<<<dim3(16, 16), 128>>>(pif_w, pif_b);
    k_gstats<<<dim3(4, 16), 256>>>();
    k_rowmean<<<512, 256>>>();
    k_gatemlp<<<16, 64>>>(gn_w, gn_b, g1_w, g1_b, g2_w, g2_b);
    k_out<<<8192, 256>>>(x, gn_w, gn_b, out);
}